// round 6
// baseline (speedup 1.0000x reference)
#include <cuda_runtime.h>

// VectorQuantizer: x [32,64,64,64] f32 (B,C,H,W), emb [512,64] f32.
// For each of N=32*64*64 pixels, argmin_k ||x - e_k||^2, write e_k back.
//
// NUMERICS: the reference's argmin is over fp32 scores
//     s_k = fl( fl(x_sq + e_sq_k) - fl(2*dot_k) ),  x_sq ~ 64
// which quantizes scores to ulp(64) ~ 7.6e-6 and creates grid-level ties
// (broken by lowest index). We must reproduce those roundings EXACTLY:
// an "exact" score (R0 version) flipped ~27 pixels -> rel_err 2e-2.
//  - x_sq: fl(x*x) then SEQUENTIAL fp32 adds (match XLA fused strided reduce)
//  - score: __fadd_rn(x_sq, e_sq) then __fsub_rn(t, 2*dot)  (no contraction)
//  - ties: strict < with ascending k == first-occurrence argmin

#define KCODES 512
#define DIM    64
#define HW     4096        // 64*64 pixels per batch image
#define TILE   128         // pixels per block

__device__ float g_esq[KCODES];

__global__ void esq_kernel(const float* __restrict__ emb) {
    int k = blockIdx.x * blockDim.x + threadIdx.x;
    if (k < KCODES) {
        const float* e = emb + k * DIM;
        float s = 0.f;
#pragma unroll
        for (int d = 0; d < DIM; ++d)
            s = __fadd_rn(s, __fmul_rn(e[d], e[d]));   // mul-then-add, sequential
        g_esq[k] = s;
    }
}

__global__ void __launch_bounds__(TILE, 4) vq_kernel(
    const float* __restrict__ x,
    const float* __restrict__ emb,
    float* __restrict__ out)
{
    const int tile = blockIdx.x;              // 0..1023
    const int b    = tile >> 5;               // 32 tiles per batch image
    const int hw   = ((tile & 31) << 7) + threadIdx.x;

    const float* xb = x + (size_t)b * DIM * HW + hw;

    // Pixel vector into registers (coalesced: consecutive lanes -> consecutive hw)
    float xv[DIM];
#pragma unroll
    for (int c = 0; c < DIM; ++c) xv[c] = xb[(size_t)c * HW];

    // x_sq exactly as the reference: fl(x*x), sequential fp32 adds over c
    float xsq = 0.f;
#pragma unroll
    for (int c = 0; c < DIM; ++c)
        xsq = __fadd_rn(xsq, __fmul_rn(xv[c], xv[c]));

    float best = 3.4e38f;
    int   bidx = 0;

    // 4 codes at a time: 4 independent FMA chains (ILP), e rows via LDG.128
    // with warp-uniform addresses (L1 broadcast; 128KB codebook stays L1-hot).
    for (int k0 = 0; k0 < KCODES; k0 += 4) {
        const float4* e0 = (const float4*)(emb + (size_t)(k0 + 0) * DIM);
        const float4* e1 = (const float4*)(emb + (size_t)(k0 + 1) * DIM);
        const float4* e2 = (const float4*)(emb + (size_t)(k0 + 2) * DIM);
        const float4* e3 = (const float4*)(emb + (size_t)(k0 + 3) * DIM);

        float a0 = 0.f, a1 = 0.f, a2 = 0.f, a3 = 0.f;
#pragma unroll
        for (int q = 0; q < DIM / 4; ++q) {
            const float4 v0 = e0[q];
            const float4 v1 = e1[q];
            const float4 v2 = e2[q];
            const float4 v3 = e3[q];
            const float x0 = xv[4 * q + 0];
            const float x1 = xv[4 * q + 1];
            const float x2 = xv[4 * q + 2];
            const float x3 = xv[4 * q + 3];
            a0 = fmaf(v0.x, x0, a0); a0 = fmaf(v0.y, x1, a0);
            a0 = fmaf(v0.z, x2, a0); a0 = fmaf(v0.w, x3, a0);
            a1 = fmaf(v1.x, x0, a1); a1 = fmaf(v1.y, x1, a1);
            a1 = fmaf(v1.z, x2, a1); a1 = fmaf(v1.w, x3, a1);
            a2 = fmaf(v2.x, x0, a2); a2 = fmaf(v2.y, x1, a2);
            a2 = fmaf(v2.z, x2, a2); a2 = fmaf(v2.w, x3, a2);
            a3 = fmaf(v3.x, x0, a3); a3 = fmaf(v3.y, x1, a3);
            a3 = fmaf(v3.z, x2, a3); a3 = fmaf(v3.w, x3, a3);
        }

        // Reference rounding pipeline: t = fl(x_sq + e_sq); s = fl(t - fl(2*dot))
        const float t0 = __fadd_rn(xsq, g_esq[k0 + 0]);
        const float t1 = __fadd_rn(xsq, g_esq[k0 + 1]);
        const float t2 = __fadd_rn(xsq, g_esq[k0 + 2]);
        const float t3 = __fadd_rn(xsq, g_esq[k0 + 3]);
        const float s0 = __fsub_rn(t0, __fmul_rn(2.f, a0));
        const float s1 = __fsub_rn(t1, __fmul_rn(2.f, a1));
        const float s2 = __fsub_rn(t2, __fmul_rn(2.f, a2));
        const float s3 = __fsub_rn(t3, __fmul_rn(2.f, a3));

        // Strict < with ascending k == first-occurrence argmin (jnp semantics)
        if (s0 < best) { best = s0; bidx = k0 + 0; }
        if (s1 < best) { best = s1; bidx = k0 + 1; }
        if (s2 < best) { best = s2; bidx = k0 + 2; }
        if (s3 < best) { best = s3; bidx = k0 + 3; }
    }

    // Gather winning code and scatter back to [B,C,H,W]
    const float* eb = emb + (size_t)bidx * DIM;
    float* ob = out + (size_t)b * DIM * HW + hw;
#pragma unroll
    for (int q = 0; q < DIM / 4; ++q) {
        const float4 v = ((const float4*)eb)[q];
        ob[(size_t)(4 * q + 0) * HW] = v.x;
        ob[(size_t)(4 * q + 1) * HW] = v.y;
        ob[(size_t)(4 * q + 2) * HW] = v.z;
        ob[(size_t)(4 * q + 3) * HW] = v.w;
    }
}

extern "C" void kernel_launch(void* const* d_in, const int* in_sizes, int n_in,
                              void* d_out, int out_size) {
    const float* x   = (const float*)d_in[0];   // [32,64,64,64]
    const float* emb = (const float*)d_in[1];   // [512,64]
    float* out = (float*)d_out;                 // [32,64,64,64]

    esq_kernel<<<1, KCODES>>>(emb);

    const int n_tiles = (32 * HW) / TILE;       // 1024
    vq_kernel<<<n_tiles, TILE>>>(x, emb, out);
}

// round 11
// speedup vs baseline: 1.9410x; 1.9410x over previous
#include <cuda_runtime.h>

// VectorQuantizer: x [32,64,64,64] f32 (B,C,H,W), emb [512,64] f32.
// For each of N=32*64*64 pixels, argmin_k ||x - e_k||^2, write e_k back.
//
// NUMERICS (validated R6, rel_err = 0.0 — DO NOT PERTURB):
//   s_k = __fsub_rn( __fadd_rn(x_sq, e_sq_k), __fmul_rn(2, dot_k) )
//   x_sq / e_sq: fl(v*v) then SEQUENTIAL fp32 adds, ascending index
//   dot_k: fmaf chain, ascending d
//   argmin: strict < with ascending k (first-occurrence, jnp semantics)
//
// R6 perf post-mortem: 573us, L1=80%, fma=20% -> L1/LSU-bound via (a) 128-reg
// cap spills, (b) per-thread LDG streaming of the whole codebook. Fix: stage
// codebook through smem in 64-code chunks (uniform LDS.128 broadcast, N=1),
// uncap registers. Same arithmetic -> still bit-exact.

#define KCODES 512
#define DIM    64
#define HW     4096        // 64*64 pixels per batch image
#define TILE   128         // pixels per block == threads per block
#define KCHUNK 64          // codes staged in smem per chunk (16 KB)

__device__ float g_esq[KCODES];

__global__ void esq_kernel(const float* __restrict__ emb) {
    int k = blockIdx.x * blockDim.x + threadIdx.x;
    if (k < KCODES) {
        const float* e = emb + k * DIM;
        float s = 0.f;
#pragma unroll
        for (int d = 0; d < DIM; ++d)
            s = __fadd_rn(s, __fmul_rn(e[d], e[d]));   // mul-then-add, sequential
        g_esq[k] = s;
    }
}

__global__ void __launch_bounds__(TILE) vq_kernel(
    const float* __restrict__ x,
    const float* __restrict__ emb,
    float* __restrict__ out)
{
    __shared__ float4 e_s[KCHUNK * (DIM / 4)];   // 64 codes x 16 float4 = 16 KB
    __shared__ float  esq_s[KCHUNK];

    const int tile = blockIdx.x;              // 0..1023
    const int b    = tile >> 5;               // 32 tiles per batch image
    const int hw   = ((tile & 31) << 7) + threadIdx.x;

    const float* xb = x + (size_t)b * DIM * HW + hw;

    // Pixel vector into registers (coalesced: consecutive lanes -> consecutive hw)
    float xv[DIM];
#pragma unroll
    for (int c = 0; c < DIM; ++c) xv[c] = xb[(size_t)c * HW];

    // x_sq exactly as the reference: fl(x*x), sequential fp32 adds over c
    float xsq = 0.f;
#pragma unroll
    for (int c = 0; c < DIM; ++c)
        xsq = __fadd_rn(xsq, __fmul_rn(xv[c], xv[c]));

    float best = 3.4e38f;
    int   bidx = 0;

    for (int chunk = 0; chunk < KCODES / KCHUNK; ++chunk) {
        __syncthreads();   // previous chunk's readers done before overwrite

        // Cooperative coalesced stage: 1024 float4 by 128 threads (8 each)
        const float4* src = (const float4*)emb + chunk * (KCHUNK * (DIM / 4));
#pragma unroll
        for (int i = 0; i < (KCHUNK * (DIM / 4)) / TILE; ++i)
            e_s[threadIdx.x + i * TILE] = src[threadIdx.x + i * TILE];
        if (threadIdx.x < KCHUNK)
            esq_s[threadIdx.x] = g_esq[chunk * KCHUNK + threadIdx.x];
        __syncthreads();

        const int kbase = chunk * KCHUNK;

        // 4 codes at a time: 4 independent FMA chains; e rows via uniform
        // LDS.128 (smem broadcast, conflict-free N=1).
        for (int kk = 0; kk < KCHUNK; kk += 4) {
            const float4* e0 = e_s + (kk + 0) * (DIM / 4);
            const float4* e1 = e_s + (kk + 1) * (DIM / 4);
            const float4* e2 = e_s + (kk + 2) * (DIM / 4);
            const float4* e3 = e_s + (kk + 3) * (DIM / 4);

            float a0 = 0.f, a1 = 0.f, a2 = 0.f, a3 = 0.f;
#pragma unroll
            for (int q = 0; q < DIM / 4; ++q) {
                const float4 v0 = e0[q];
                const float4 v1 = e1[q];
                const float4 v2 = e2[q];
                const float4 v3 = e3[q];
                const float x0 = xv[4 * q + 0];
                const float x1 = xv[4 * q + 1];
                const float x2 = xv[4 * q + 2];
                const float x3 = xv[4 * q + 3];
                a0 = fmaf(v0.x, x0, a0); a0 = fmaf(v0.y, x1, a0);
                a0 = fmaf(v0.z, x2, a0); a0 = fmaf(v0.w, x3, a0);
                a1 = fmaf(v1.x, x0, a1); a1 = fmaf(v1.y, x1, a1);
                a1 = fmaf(v1.z, x2, a1); a1 = fmaf(v1.w, x3, a1);
                a2 = fmaf(v2.x, x0, a2); a2 = fmaf(v2.y, x1, a2);
                a2 = fmaf(v2.z, x2, a2); a2 = fmaf(v2.w, x3, a2);
                a3 = fmaf(v3.x, x0, a3); a3 = fmaf(v3.y, x1, a3);
                a3 = fmaf(v3.z, x2, a3); a3 = fmaf(v3.w, x3, a3);
            }

            // Reference rounding pipeline: t = fl(x_sq + e_sq); s = fl(t - fl(2*dot))
            const float t0 = __fadd_rn(xsq, esq_s[kk + 0]);
            const float t1 = __fadd_rn(xsq, esq_s[kk + 1]);
            const float t2 = __fadd_rn(xsq, esq_s[kk + 2]);
            const float t3 = __fadd_rn(xsq, esq_s[kk + 3]);
            const float s0 = __fsub_rn(t0, __fmul_rn(2.f, a0));
            const float s1 = __fsub_rn(t1, __fmul_rn(2.f, a1));
            const float s2 = __fsub_rn(t2, __fmul_rn(2.f, a2));
            const float s3 = __fsub_rn(t3, __fmul_rn(2.f, a3));

            // Strict < with ascending k == first-occurrence argmin
            if (s0 < best) { best = s0; bidx = kbase + kk + 0; }
            if (s1 < best) { best = s1; bidx = kbase + kk + 1; }
            if (s2 < best) { best = s2; bidx = kbase + kk + 2; }
            if (s3 < best) { best = s3; bidx = kbase + kk + 3; }
        }
    }

    // Gather winning code (from global; codebook is L2-hot) and scatter to [B,C,H,W]
    const float* eb = emb + (size_t)bidx * DIM;
    float* ob = out + (size_t)b * DIM * HW + hw;
#pragma unroll
    for (int q = 0; q < DIM / 4; ++q) {
        const float4 v = ((const float4*)eb)[q];
        ob[(size_t)(4 * q + 0) * HW] = v.x;
        ob[(size_t)(4 * q + 1) * HW] = v.y;
        ob[(size_t)(4 * q + 2) * HW] = v.z;
        ob[(size_t)(4 * q + 3) * HW] = v.w;
    }
}

extern "C" void kernel_launch(void* const* d_in, const int* in_sizes, int n_in,
                              void* d_out, int out_size) {
    const float* x   = (const float*)d_in[0];   // [32,64,64,64]
    const float* emb = (const float*)d_in[1];   // [512,64]
    float* out = (float*)d_out;                 // [32,64,64,64]

    esq_kernel<<<1, KCODES>>>(emb);

    const int n_tiles = (32 * HW) / TILE;       // 1024
    vq_kernel<<<n_tiles, TILE>>>(x, emb, out);
}

// round 12
// speedup vs baseline: 2.4124x; 1.2429x over previous
#include <cuda_runtime.h>

// VectorQuantizer: x [32,64,64,64] f32 (B,C,H,W), emb [512,64] f32.
// For each of N=32*64*64 pixels, argmin_k ||x - e_k||^2, write e_k back.
//
// NUMERICS (validated R6, rel_err = 0.0 — DO NOT PERTURB):
//   s_k = __fsub_rn( __fadd_rn(x_sq, e_sq_k), __fmul_rn(2, dot_k) )
//   x_sq / e_sq: fl(v*v) then SEQUENTIAL fp32 adds, ascending index
//   dot_k: fma chain, ascending d       (fma.rn.f32x2 lane == fmaf bit-exact)
//   argmin: strict < with ascending k (first-occurrence, jnp semantics)
//
// R11 post-mortem: 282us sat simultaneously on the scalar-FFMA ceiling
// (rt 2/cyc/SM -> 244us floor) and the LDS ceiling (LDS.128 = 2 wavefronts
// -> 244us floor). This version packs TWO ADJACENT PIXELS into f32x2 lanes:
//  - FFMA2 halves fma-pipe instructions (67M -> 221k cyc/SM)
//  - 2 px/thread halves LDS wavefronts  (codebook read amortized)
//  - {e,e} operand built by mov.b64 on the otherwise-idle ALU pipe

#define KCODES 512
#define DIM    64
#define HW     4096        // 64*64 pixels per batch image
#define TILE   64          // threads per block
#define PXB    128         // pixels per block (2 adjacent px per thread)
#define KCHUNK 64          // codes staged in smem per chunk (16 KB)

__device__ float g_esq[KCODES];

__global__ void esq_kernel(const float* __restrict__ emb) {
    int k = blockIdx.x * blockDim.x + threadIdx.x;
    if (k < KCODES) {
        const float* e = emb + k * DIM;
        float s = 0.f;
#pragma unroll
        for (int d = 0; d < DIM; ++d)
            s = __fadd_rn(s, __fmul_rn(e[d], e[d]));   // mul-then-add, sequential
        g_esq[k] = s;
    }
}

// pack {e,e} (ALU pipe), then packed FMA: acc.lane += e * x.lane (fma pipe).
// Each f32x2 lane is an IEEE-RN fp32 FMA == fmaf, so per-pixel dot chains
// remain bit-identical to the R6-validated scalar version.
#define FFMA2_STEP(acc, ev, xp)                                   \
    do {                                                          \
        unsigned long long _ee;                                   \
        asm("mov.b64 %0, {%1, %1};" : "=l"(_ee) : "f"(ev));       \
        asm("fma.rn.f32x2 %0, %1, %2, %0;"                        \
            : "+l"(acc) : "l"(_ee), "l"(xp));                     \
    } while (0)

__global__ void __launch_bounds__(TILE) vq_kernel(
    const float* __restrict__ x,
    const float* __restrict__ emb,
    float* __restrict__ out)
{
    __shared__ float4 e_s[KCHUNK * (DIM / 4)];   // 64 codes x 16 float4 = 16 KB
    __shared__ float  esq_s[KCHUNK];

    const int tile = blockIdx.x;                 // 0..1023
    const int b    = tile >> 5;                  // 32 tiles (128 px) per image
    const int px0  = ((tile & 31) * PXB) + (threadIdx.x << 1);  // even

    const float* xb = x + (size_t)b * DIM * HW + px0;

    // Two adjacent pixels per thread, packed {xA, xB} per channel.
    // float2 loads stay coalesced (64 consecutive pairs per 2-warp block).
    unsigned long long xv[DIM];
    float xsqA = 0.f, xsqB = 0.f;
#pragma unroll
    for (int c = 0; c < DIM; ++c) {
        const float2 v = *(const float2*)(xb + (size_t)c * HW);
        xsqA = __fadd_rn(xsqA, __fmul_rn(v.x, v.x));   // sequential, ascending c
        xsqB = __fadd_rn(xsqB, __fmul_rn(v.y, v.y));
        asm("mov.b64 %0, {%1, %2};" : "=l"(xv[c]) : "f"(v.x), "f"(v.y));
    }

    float bestA = 3.4e38f, bestB = 3.4e38f;
    int   biA = 0, biB = 0;

    for (int chunk = 0; chunk < KCODES / KCHUNK; ++chunk) {
        __syncthreads();   // previous chunk's readers done before overwrite

        // Cooperative coalesced stage: 1024 float4 by 64 threads (16 each)
        const float4* src = (const float4*)emb + chunk * (KCHUNK * (DIM / 4));
#pragma unroll
        for (int i = 0; i < (KCHUNK * (DIM / 4)) / TILE; ++i)
            e_s[threadIdx.x + i * TILE] = src[threadIdx.x + i * TILE];
        esq_s[threadIdx.x] = g_esq[chunk * KCHUNK + threadIdx.x];  // TILE==KCHUNK
        __syncthreads();

        const int kbase = chunk * KCHUNK;

        // kk loop kept DYNAMIC so the hot body stays I$-resident (~10KB).
        for (int kk = 0; kk < KCHUNK; kk += 4) {
            const float4* e0 = e_s + (kk + 0) * (DIM / 4);
            const float4* e1 = e_s + (kk + 1) * (DIM / 4);
            const float4* e2 = e_s + (kk + 2) * (DIM / 4);
            const float4* e3 = e_s + (kk + 3) * (DIM / 4);

            unsigned long long a0 = 0ull, a1 = 0ull, a2 = 0ull, a3 = 0ull;
#pragma unroll
            for (int q = 0; q < DIM / 4; ++q) {
                const float4 v0 = e0[q];
                const float4 v1 = e1[q];
                const float4 v2 = e2[q];
                const float4 v3 = e3[q];
                const unsigned long long xq0 = xv[4 * q + 0];
                const unsigned long long xq1 = xv[4 * q + 1];
                const unsigned long long xq2 = xv[4 * q + 2];
                const unsigned long long xq3 = xv[4 * q + 3];
                FFMA2_STEP(a0, v0.x, xq0); FFMA2_STEP(a0, v0.y, xq1);
                FFMA2_STEP(a0, v0.z, xq2); FFMA2_STEP(a0, v0.w, xq3);
                FFMA2_STEP(a1, v1.x, xq0); FFMA2_STEP(a1, v1.y, xq1);
                FFMA2_STEP(a1, v1.z, xq2); FFMA2_STEP(a1, v1.w, xq3);
                FFMA2_STEP(a2, v2.x, xq0); FFMA2_STEP(a2, v2.y, xq1);
                FFMA2_STEP(a2, v2.z, xq2); FFMA2_STEP(a2, v2.w, xq3);
                FFMA2_STEP(a3, v3.x, xq0); FFMA2_STEP(a3, v3.y, xq1);
                FFMA2_STEP(a3, v3.z, xq2); FFMA2_STEP(a3, v3.w, xq3);
            }

            // Unpack packed dots, then the frozen scalar rounding pipeline.
            float d0A, d0B, d1A, d1B, d2A, d2B, d3A, d3B;
            asm("mov.b64 {%0, %1}, %2;" : "=f"(d0A), "=f"(d0B) : "l"(a0));
            asm("mov.b64 {%0, %1}, %2;" : "=f"(d1A), "=f"(d1B) : "l"(a1));
            asm("mov.b64 {%0, %1}, %2;" : "=f"(d2A), "=f"(d2B) : "l"(a2));
            asm("mov.b64 {%0, %1}, %2;" : "=f"(d3A), "=f"(d3B) : "l"(a3));

            const float q0 = esq_s[kk + 0];
            const float q1 = esq_s[kk + 1];
            const float q2 = esq_s[kk + 2];
            const float q3 = esq_s[kk + 3];

            // pixel A: t = fl(x_sq + e_sq); s = fl(t - fl(2*dot)); ascending k
            const float sA0 = __fsub_rn(__fadd_rn(xsqA, q0), __fmul_rn(2.f, d0A));
            const float sA1 = __fsub_rn(__fadd_rn(xsqA, q1), __fmul_rn(2.f, d1A));
            const float sA2 = __fsub_rn(__fadd_rn(xsqA, q2), __fmul_rn(2.f, d2A));
            const float sA3 = __fsub_rn(__fadd_rn(xsqA, q3), __fmul_rn(2.f, d3A));
            if (sA0 < bestA) { bestA = sA0; biA = kbase + kk + 0; }
            if (sA1 < bestA) { bestA = sA1; biA = kbase + kk + 1; }
            if (sA2 < bestA) { bestA = sA2; biA = kbase + kk + 2; }
            if (sA3 < bestA) { bestA = sA3; biA = kbase + kk + 3; }

            // pixel B
            const float sB0 = __fsub_rn(__fadd_rn(xsqB, q0), __fmul_rn(2.f, d0B));
            const float sB1 = __fsub_rn(__fadd_rn(xsqB, q1), __fmul_rn(2.f, d1B));
            const float sB2 = __fsub_rn(__fadd_rn(xsqB, q2), __fmul_rn(2.f, d2B));
            const float sB3 = __fsub_rn(__fadd_rn(xsqB, q3), __fmul_rn(2.f, d3B));
            if (sB0 < bestB) { bestB = sB0; biB = kbase + kk + 0; }
            if (sB1 < bestB) { bestB = sB1; biB = kbase + kk + 1; }
            if (sB2 < bestB) { bestB = sB2; biB = kbase + kk + 2; }
            if (sB3 < bestB) { bestB = sB3; biB = kbase + kk + 3; }
        }
    }

    // Gather winning codes (L2-hot) and scatter both pixels with float2 stores.
    const float* eA = emb + (size_t)biA * DIM;
    const float* eB = emb + (size_t)biB * DIM;
    float* ob = out + (size_t)b * DIM * HW + px0;
#pragma unroll
    for (int q = 0; q < DIM / 4; ++q) {
        const float4 va = ((const float4*)eA)[q];
        const float4 vb = ((const float4*)eB)[q];
        *(float2*)(ob + (size_t)(4 * q + 0) * HW) = make_float2(va.x, vb.x);
        *(float2*)(ob + (size_t)(4 * q + 1) * HW) = make_float2(va.y, vb.y);
        *(float2*)(ob + (size_t)(4 * q + 2) * HW) = make_float2(va.z, vb.z);
        *(float2*)(ob + (size_t)(4 * q + 3) * HW) = make_float2(va.w, vb.w);
    }
}

extern "C" void kernel_launch(void* const* d_in, const int* in_sizes, int n_in,
                              void* d_out, int out_size) {
    const float* x   = (const float*)d_in[0];   // [32,64,64,64]
    const float* emb = (const float*)d_in[1];   // [512,64]
    float* out = (float*)d_out;                 // [32,64,64,64]

    esq_kernel<<<1, KCODES>>>(emb);

    const int n_tiles = (32 * HW) / PXB;        // 1024 blocks, 128 px each
    vq_kernel<<<n_tiles, TILE>>>(x, emb, out);
}